// round 2
// baseline (speedup 1.0000x reference)
#include <cuda_runtime.h>

// WaveNet block: 8 layers, C=256, K=2, dilations 1..128, B=16, T=4096.
// Per layer: F = tanh(convF(Z)), G = sigmoid(convG(Z)), Z = F*G, Zout += Z.
// Each conv = 2-tap dilated causal conv = dual GEMM over (co, ci) with
// current and delayed activations.

#define LAYERS 8
#define C 256
#define T 4096
#define B 16
#define CT (C * T)          // 1048576 elems per batch image
#define KC 16               // ci chunk
#define CO_TILE 128
#define N_TILE 64
#define WPAD 130            // padded row for W smem (conflict-free)

typedef unsigned long long ull;

// Ping-pong activation buffers (64 MiB each) — __device__ globals, no allocation.
__device__ float g_z0[(size_t)B * CT];
__device__ float g_z1[(size_t)B * CT];

__device__ __forceinline__ ull dup2(float x) {
    ull r; asm("mov.b64 %0, {%1, %1};" : "=l"(r) : "f"(x)); return r;
}
__device__ __forceinline__ ull fma2(ull a, ull b, ull c) {
    ull d; asm("fma.rn.f32x2 %0, %1, %2, %3;" : "=l"(d) : "l"(a), "l"(b), "l"(c)); return d;
}
__device__ __forceinline__ float2 unpk(ull a) {
    float lo, hi; asm("mov.b64 {%0, %1}, %2;" : "=f"(lo), "=f"(hi) : "l"(a));
    return make_float2(lo, hi);
}

__device__ __forceinline__ float sigm_f(float x) {
    return 1.0f / (1.0f + __expf(-x));
}
__device__ __forceinline__ float tanh_f(float x) {
    return 2.0f / (1.0f + __expf(-2.0f * x)) - 1.0f;
}
__device__ __forceinline__ float act(float f, float g) {
    return tanh_f(f) * sigm_f(g);
}

__global__ __launch_bounds__(256, 2)
void wavenet_layer(const float* __restrict__ ys,
                   const float* __restrict__ fw, const float* __restrict__ fb,
                   const float* __restrict__ gw, const float* __restrict__ gb,
                   int src_sel, int dst_sel, int d,
                   int first, int write_next,
                   float* __restrict__ out)
{
    __shared__ float Xc[KC][N_TILE];   // current-tap activations
    __shared__ float Xd[KC][N_TILE];   // delayed-tap activations (t - d)
    __shared__ float Wf0[KC][WPAD];    // filter tap0 (delayed)
    __shared__ float Wf1[KC][WPAD];    // filter tap1 (current)
    __shared__ float Wg0[KC][WPAD];
    __shared__ float Wg1[KC][WPAD];

    const float* zin = (src_sel == 0) ? ys : (src_sel == 1 ? g_z0 : g_z1);
    float* znext = (dst_sel == 1) ? g_z0 : g_z1;

    const int tid = threadIdx.x;
    const int tx = tid & 15;        // n direction (4 n each)
    const int ty = tid >> 4;        // co direction (8 co each, as 4 pairs)
    const int t0 = blockIdx.x * N_TILE;
    const int b  = blockIdx.y;
    const int co0 = blockIdx.z * CO_TILE;

    // Accumulators: [co-pair j][n], each ull = packed f32x2 over (co, co+1)
    ull accF[4][4], accG[4][4];
    #pragma unroll
    for (int j = 0; j < 4; j++)
        #pragma unroll
        for (int n = 0; n < 4; n++) { accF[j][n] = 0ull; accG[j][n] = 0ull; }

    const float* xbase = zin + (size_t)b * CT;
    const int lrow = tid >> 4;          // 0..15 : ci row within chunk
    const int lcq  = (tid & 15) * 4;    // 0..60 : col within tile

    for (int ci0 = 0; ci0 < C; ci0 += KC) {
        // --- load X tiles (current + delayed) ---
        {
            const float* xrow = xbase + (size_t)(ci0 + lrow) * T;
            *(float4*)&Xc[lrow][lcq] = *(const float4*)(xrow + t0 + lcq);
            const int tb = t0 + lcq - d;
            #pragma unroll
            for (int j = 0; j < 4; j++)
                Xd[lrow][lcq + j] = (tb + j >= 0) ? xrow[tb + j] : 0.0f;
        }
        // --- load W tiles (taps interleaved in gmem -> split in smem) ---
        #pragma unroll
        for (int i = tid; i < KC * CO_TILE; i += 256) {
            const int kk = i & (KC - 1);
            const int co = i >> 4;
            const float2 wf = *(const float2*)(fw + ((size_t)(co0 + co) * C + (ci0 + kk)) * 2);
            const float2 wg = *(const float2*)(gw + ((size_t)(co0 + co) * C + (ci0 + kk)) * 2);
            Wf0[kk][co] = wf.x; Wf1[kk][co] = wf.y;
            Wg0[kk][co] = wg.x; Wg1[kk][co] = wg.y;
        }
        __syncthreads();

        // --- inner product over this ci chunk ---
        #pragma unroll
        for (int kk = 0; kk < KC; kk++) {
            const float4 xc4 = *(const float4*)&Xc[kk][tx * 4];
            const float4 xd4 = *(const float4*)&Xd[kk][tx * 4];
            ull xc[4] = { dup2(xc4.x), dup2(xc4.y), dup2(xc4.z), dup2(xc4.w) };
            ull xd[4] = { dup2(xd4.x), dup2(xd4.y), dup2(xd4.z), dup2(xd4.w) };
            #pragma unroll
            for (int j = 0; j < 4; j++) {
                const int cob = ty * 8 + j * 2;   // even -> 8B aligned
                const ull wf1 = *(const ull*)&Wf1[kk][cob];
                const ull wf0 = *(const ull*)&Wf0[kk][cob];
                const ull wg1 = *(const ull*)&Wg1[kk][cob];
                const ull wg0 = *(const ull*)&Wg0[kk][cob];
                #pragma unroll
                for (int n = 0; n < 4; n++) {
                    accF[j][n] = fma2(wf1, xc[n], accF[j][n]);
                    accF[j][n] = fma2(wf0, xd[n], accF[j][n]);
                    accG[j][n] = fma2(wg1, xc[n], accG[j][n]);
                    accG[j][n] = fma2(wg0, xd[n], accG[j][n]);
                }
            }
        }
        __syncthreads();
    }

    // --- epilogue: bias + tanh*sigmoid + write znext + accumulate Zout ---
    #pragma unroll
    for (int j = 0; j < 4; j++) {
        float2 F[4], G[4];
        #pragma unroll
        for (int n = 0; n < 4; n++) { F[n] = unpk(accF[j][n]); G[n] = unpk(accG[j][n]); }
        #pragma unroll
        for (int lane = 0; lane < 2; lane++) {
            const int co = co0 + ty * 8 + j * 2 + lane;
            const float fbv = fb[co];
            const float gbv = gb[co];
            float4 z;
            if (lane == 0) {
                z.x = act(F[0].x + fbv, G[0].x + gbv);
                z.y = act(F[1].x + fbv, G[1].x + gbv);
                z.z = act(F[2].x + fbv, G[2].x + gbv);
                z.w = act(F[3].x + fbv, G[3].x + gbv);
            } else {
                z.x = act(F[0].y + fbv, G[0].y + gbv);
                z.y = act(F[1].y + fbv, G[1].y + gbv);
                z.z = act(F[2].y + fbv, G[2].y + gbv);
                z.w = act(F[3].y + fbv, G[3].y + gbv);
            }
            const size_t off = (size_t)b * CT + (size_t)co * T + t0 + tx * 4;
            if (write_next)
                *(float4*)(znext + off) = z;
            if (first) {
                *(float4*)(out + off) = z;
            } else {
                float4 o = *(const float4*)(out + off);
                o.x += z.x; o.y += z.y; o.z += z.z; o.w += z.w;
                *(float4*)(out + off) = o;
            }
        }
    }
}

extern "C" void kernel_launch(void* const* d_in, const int* in_sizes, int n_in,
                              void* d_out, int out_size)
{
    const float* ys = (const float*)d_in[0];
    const float* fw = (const float*)d_in[1];
    const float* fb = (const float*)d_in[2];
    const float* gw = (const float*)d_in[3];
    const float* gb = (const float*)d_in[4];
    float* out = (float*)d_out;

    dim3 grid(T / N_TILE, B, C / CO_TILE);
    int src = 0;      // 0 = ys, 1 = g_z0, 2 = g_z1
    int dst = 1;
    for (int l = 0; l < LAYERS; l++) {
        wavenet_layer<<<grid, 256>>>(
            ys,
            fw + (size_t)l * C * C * 2, fb + (size_t)l * C,
            gw + (size_t)l * C * C * 2, gb + (size_t)l * C,
            src, dst, 1 << l,
            (l == 0) ? 1 : 0,
            (l != LAYERS - 1) ? 1 : 0,
            out);
        src = dst;
        dst = (dst == 1) ? 2 : 1;
    }
}

// round 11
// speedup vs baseline: 2.1813x; 2.1813x over previous
#include <cuda_runtime.h>
#include <cuda_bf16.h>

#define LAYERS 8
#define C 256
#define T 4096
#define B 16

typedef unsigned int u32;
typedef unsigned long long u64;

// ---------------- device global scratch (no allocation) ----------------
// activations, transposed [buf][b][t][ci], split hi/lo bf16 planes
__device__ __nv_bfloat16 g_zh[2][(size_t)B * T * C];
__device__ __nv_bfloat16 g_zl[2][(size_t)B * T * C];
// packed, PRE-SWIZZLED weights: [l][cb][ch][r=0..255][64]  (r = 2*co_local + conv)
__device__ __nv_bfloat16 g_wh[(size_t)LAYERS * 2 * 8 * 256 * 64];
__device__ __nv_bfloat16 g_wl[(size_t)LAYERS * 2 * 8 * 256 * 64];

// ---------------- helpers ----------------
__device__ __forceinline__ u32 smem_u32(const void* p) {
    u32 a;
    asm("{ .reg .u64 t; cvta.to.shared.u64 t, %1; cvt.u32.u64 %0, t; }" : "=r"(a) : "l"(p));
    return a;
}
__device__ __forceinline__ void split_bf(float v, __nv_bfloat16& h, __nv_bfloat16& l) {
    h = __float2bfloat16(v);
    l = __float2bfloat16(v - __bfloat162float(h));
}
__device__ __forceinline__ float actf(float f, float g) {
    float tf = 2.0f / (1.0f + __expf(-2.0f * f)) - 1.0f;
    float sg = 1.0f / (1.0f + __expf(-g));
    return tf * sg;
}
__device__ __forceinline__ void cpa(u32 dst, const void* src, u32 srcsz) {
    asm volatile("cp.async.cg.shared.global [%0], [%1], 16, %2;"
                 :: "r"(dst), "l"(src), "r"(srcsz) : "memory");
}
__device__ __forceinline__ void cpa_commit() {
    asm volatile("cp.async.commit_group;" ::: "memory");
}
__device__ __forceinline__ void ldsm4(u32& r0, u32& r1, u32& r2, u32& r3, u32 addr) {
    asm volatile("ldmatrix.sync.aligned.m8n8.x4.shared.b16 {%0,%1,%2,%3}, [%4];"
                 : "=r"(r0), "=r"(r1), "=r"(r2), "=r"(r3) : "r"(addr));
}
__device__ __forceinline__ void mma_bf16(float* d, const u32* a, const u32* b) {
    asm volatile("mma.sync.aligned.m16n8k16.row.col.f32.bf16.bf16.f32 "
                 "{%0,%1,%2,%3}, {%4,%5,%6,%7}, {%8,%9}, {%0,%1,%2,%3};"
                 : "+f"(d[0]), "+f"(d[1]), "+f"(d[2]), "+f"(d[3])
                 : "r"(a[0]), "r"(a[1]), "r"(a[2]), "r"(a[3]), "r"(b[0]), "r"(b[1]));
}

// ---------------- pre-kernels ----------------
// Pack weights: k = tap*256 + ci (tap0 = delayed), row r = 2*co_local + conv,
// SW128 swizzle baked into the 64-element row (elem col = kc ^ ((r&7)<<3)).
__global__ void cvt_weights(const float* __restrict__ fw, const float* __restrict__ gw) {
    int idx = blockIdx.x * 256 + threadIdx.x;
    if (idx >= LAYERS * C * C * 2) return;
    int tap = idx & 1;
    int ci = (idx >> 1) & 255;
    int co = (idx >> 9) & 255;
    int l  = idx >> 17;
    int k  = tap * 256 + ci;
    int ch = k >> 6, kc = k & 63;
    int cb = co >> 7;
    #pragma unroll
    for (int conv = 0; conv < 2; conv++) {
        int r = ((co & 127) << 1) | conv;
        size_t dst = (((size_t)(l * 2 + cb) * 8 + ch) * 256 + r) * 64
                   + (kc ^ ((r & 7) << 3));
        float v = conv ? gw[idx] : fw[idx];
        split_bf(v, g_wh[dst], g_wl[dst]);
    }
}

// Transpose ys [b][c][t] -> g_z[0][b][t][c] split hi/lo.
__global__ void cvt_x(const float* __restrict__ ys) {
    __shared__ float tile[32][33];
    int b = blockIdx.z, t0 = blockIdx.x * 32, c0 = blockIdx.y * 32;
    int tx = threadIdx.x, ty = threadIdx.y;
    #pragma unroll
    for (int i = 0; i < 4; i++) {
        int cc = ty + i * 8;
        tile[cc][tx] = ys[((size_t)b * C + c0 + cc) * T + t0 + tx];
    }
    __syncthreads();
    #pragma unroll
    for (int i = 0; i < 4; i++) {
        int tt = ty + i * 8;
        size_t off = ((size_t)b * T + t0 + tt) * C + c0 + tx;
        split_bf(tile[tx][tt], g_zh[0][off], g_zl[0][off]);
    }
}

// ---------------- main layer kernel ----------------
// CTA: M=256 rows (128 co x {F,G} interleaved) x N=128 t, K=512 in 8 chunks of 64.
// SMEM per stage: Ah 32K | Al 32K | Bh 16K | Bl 16K = 96K, double buffered.
#define STAGE_BYTES 98304
#define SMEM_TOTAL (2 * STAGE_BYTES)

__global__ __launch_bounds__(512, 1)
void wn_gemm(const float* __restrict__ fb, const float* __restrict__ gb,
             float* __restrict__ out,
             int rd, int l, int d, int first, int wnext)
{
    extern __shared__ __align__(1024) char smem[];
    const u32 sb = smem_u32(smem);
    const int tid = threadIdx.x;
    const int lane = tid & 31, wid = tid >> 5;
    const int wm = wid & 7, wn = wid >> 3;      // 8 m-warps x 2 n-warps
    const int t0 = blockIdx.x * 128;
    const int b  = blockIdx.y;
    const int cb = blockIdx.z;
    const int co0 = cb * 128;

    const __nv_bfloat16* xh = g_zh[rd];
    const __nv_bfloat16* xl = g_zl[rd];

    float acc[2][8][4];
    #pragma unroll
    for (int mi = 0; mi < 2; mi++)
        #pragma unroll
        for (int ni = 0; ni < 8; ni++)
            #pragma unroll
            for (int e = 0; e < 4; e++) acc[mi][ni][e] = 0.0f;

    // ---- stage loader ----
    const size_t wblob = (size_t)(l * 2 + cb) * 8 * 16384;
    const int brow = tid >> 2;            // 0..127 (t row)
    const int bc0  = (tid & 3) * 2;       // 2 chunks of 16B per plane

    auto load_stage = [&](int ch, int s) {
        const u32 base = sb + s * STAGE_BYTES;
        // A: linear copy of pre-swizzled 32KB blobs (hi & lo)
        const char* gah = (const char*)(g_wh + wblob + (size_t)ch * 16384);
        const char* gal = (const char*)(g_wl + wblob + (size_t)ch * 16384);
        #pragma unroll
        for (int j = 0; j < 4; j++) {
            int off = (tid + j * 512) * 16;
            cpa(base + off,         gah + off, 16);
            cpa(base + 32768 + off, gal + off, 16);
        }
        // B: X[t rows][64 ci] with SW128 swizzle; delayed tap shifts rows by -d
        const int delayed = (ch < 4);
        const int ci0 = (ch & 3) * 64;
        const int trow = t0 + brow - (delayed ? d : 0);
        const u32 ssz = (trow >= 0) ? 16u : 0u;
        const int trc = (trow >= 0) ? trow : 0;
        const size_t go = ((size_t)b * T + trc) * C + ci0;
        #pragma unroll
        for (int j = 0; j < 2; j++) {
            int c = bc0 + j;
            u32 doff = brow * 128 + ((c * 16) ^ ((brow & 7) << 4));
            cpa(base + 65536 + doff, (const char*)(xh + go + c * 8), ssz);
            cpa(base + 81920 + doff, (const char*)(xl + go + c * 8), ssz);
        }
    };

    // lane-invariant fragment addressing
    const int rA = (lane & 7) + (lane & 8);          // A row within m16
    const int cAh = (lane >> 4);                     // A 16B chunk half
    const int rB = (lane & 7) + ((lane >> 4) << 3);  // B row within n16
    const int cBh = ((lane >> 3) & 1);               // B 16B chunk half

    auto compute = [&](int s) {
        const u32 base = sb + s * STAGE_BYTES;
        const u32 Ah = base, Al = base + 32768, Bh = base + 65536, Bl = base + 81920;
        // K chunk is 64 wide = FOUR k16 blocks (16B chunk pairs {0,1}..{6,7}).
        #pragma unroll
        for (int ks = 0; ks < 4; ks++) {
            u32 bfr[8][2], ah[2][4], al[2][4];
            const int cB = ks * 2 + cBh;
            const int cA = ks * 2 + cAh;
            // B hi frags: 4 x ldmatrix.x4 covering n 0..63
            #pragma unroll
            for (int g = 0; g < 4; g++) {
                int row = wn * 64 + g * 16 + rB;
                u32 ad = Bh + row * 128 + ((cB * 16) ^ ((row & 7) << 4));
                ldsm4(bfr[2 * g][0], bfr[2 * g][1], bfr[2 * g + 1][0], bfr[2 * g + 1][1], ad);
            }
            // A hi frags
            #pragma unroll
            for (int mi = 0; mi < 2; mi++) {
                int row = wm * 32 + mi * 16 + rA;
                u32 ad = Ah + row * 128 + ((cA * 16) ^ ((row & 7) << 4));
                ldsm4(ah[mi][0], ah[mi][1], ah[mi][2], ah[mi][3], ad);
            }
            // hh
            #pragma unroll
            for (int mi = 0; mi < 2; mi++)
                #pragma unroll
                for (int ni = 0; ni < 8; ni++) mma_bf16(acc[mi][ni], ah[mi], bfr[ni]);
            // A lo frags -> lh
            #pragma unroll
            for (int mi = 0; mi < 2; mi++) {
                int row = wm * 32 + mi * 16 + rA;
                u32 ad = Al + row * 128 + ((cA * 16) ^ ((row & 7) << 4));
                ldsm4(al[mi][0], al[mi][1], al[mi][2], al[mi][3], ad);
            }
            #pragma unroll
            for (int mi = 0; mi < 2; mi++)
                #pragma unroll
                for (int ni = 0; ni < 8; ni++) mma_bf16(acc[mi][ni], al[mi], bfr[ni]);
            // B lo frags (reuse regs) -> hl
            #pragma unroll
            for (int g = 0; g < 4; g++) {
                int row = wn * 64 + g * 16 + rB;
                u32 ad = Bl + row * 128 + ((cB * 16) ^ ((row & 7) << 4));
                ldsm4(bfr[2 * g][0], bfr[2 * g][1], bfr[2 * g + 1][0], bfr[2 * g + 1][1], ad);
            }
            #pragma unroll
            for (int mi = 0; mi < 2; mi++)
                #pragma unroll
                for (int ni = 0; ni < 8; ni++) mma_bf16(acc[mi][ni], ah[mi], bfr[ni]);
        }
    };

    // ---- pipelined main loop ----
    load_stage(0, 0); cpa_commit();
    load_stage(1, 1); cpa_commit();
    for (int ch = 0; ch < 8; ch++) {
        asm volatile("cp.async.wait_group 1;" ::: "memory");
        __syncthreads();
        compute(ch & 1);
        __syncthreads();
        if (ch + 2 < 8) load_stage(ch + 2, ch & 1);
        cpa_commit();
    }

    // ---- epilogue: pair F/G via shfl_xor(4), act, write Zout + next Z ----
    __nv_bfloat16* zh = g_zh[rd ^ 1];
    __nv_bfloat16* zl = g_zl[rd ^ 1];
    const int q = lane >> 2;
    const int tcol = t0 + wn * 64 + (lane & 3) * 2;
    const int qodd = q & 1;
    #pragma unroll
    for (int mi = 0; mi < 2; mi++) {
        #pragma unroll
        for (int ni = 0; ni < 8; ni++) {
            float p0 = __shfl_xor_sync(0xffffffffu, acc[mi][ni][0], 4);
            float p1 = __shfl_xor_sync(0xffffffffu, acc[mi][ni][1], 4);
            float p2 = __shfl_xor_sync(0xffffffffu, acc[mi][ni][2], 4);
            float p3 = __shfl_xor_sync(0xffffffffu, acc[mi][ni][3], 4);
            // even q: handle rows (q, q+1) -> co base;   F = own d0,d1; G = partner d0,d1
            // odd  q: handle rows (q+7, q+8) -> co base+4; F = partner d2,d3; G = own d2,d3
            float f0, f1, g0, g1;
            if (!qodd) { f0 = acc[mi][ni][0]; f1 = acc[mi][ni][1]; g0 = p0; g1 = p1; }
            else       { f0 = p2; f1 = p3; g0 = acc[mi][ni][2]; g1 = acc[mi][ni][3]; }
            const int co = co0 + wm * 16 + mi * 8 + (q >> 1) + qodd * 4;
            const float fbv = __ldg(fb + co);
            const float gbv = __ldg(gb + co);
            const int t = tcol + ni * 8;
            float z0 = actf(f0 + fbv, g0 + gbv);
            float z1 = actf(f1 + fbv, g1 + gbv);
            const size_t oo = ((size_t)b * C + co) * T + t;
            float2 v = make_float2(z0, z1);
            if (!first) {
                float2 p = *(const float2*)(out + oo);
                v.x += p.x; v.y += p.y;
            }
            *(float2*)(out + oo) = v;
            if (wnext) {
                const size_t zb = ((size_t)b * T + t) * C + co;
                split_bf(z0, zh[zb], zl[zb]);
                split_bf(z1, zh[zb + C], zl[zb + C]);
            }
        }
    }
}

// ---------------- launch ----------------
extern "C" void kernel_launch(void* const* d_in, const int* in_sizes, int n_in,
                              void* d_out, int out_size)
{
    const float* ys = (const float*)d_in[0];
    const float* fw = (const float*)d_in[1];
    const float* fb = (const float*)d_in[2];
    const float* gw = (const float*)d_in[3];
    const float* gb = (const float*)d_in[4];
    float* out = (float*)d_out;

    cudaFuncSetAttribute(wn_gemm, cudaFuncAttributeMaxDynamicSharedMemorySize, SMEM_TOTAL);

    cvt_weights<<<(LAYERS * C * C * 2 + 255) / 256, 256>>>(fw, gw);
    cvt_x<<<dim3(T / 32, C / 32, B), dim3(32, 8)>>>(ys);

    dim3 grid(T / 128, B, 2);
    for (int l = 0; l < LAYERS; l++) {
        wn_gemm<<<grid, 512, SMEM_TOTAL>>>(
            fb + (size_t)l * C, gb + (size_t)l * C, out,
            l & 1, l, 1 << l,
            (l == 0) ? 1 : 0, (l != LAYERS - 1) ? 1 : 0);
    }
}